// round 17
// baseline (speedup 1.0000x reference)
#include <cuda_runtime.h>
#include <cuda_fp16.h>
#include <cstdint>

#define Bb 128
#define Tt 1024
#define Dd 256
#define Hh 512
#define Oo 128
#define G4H 2048

#define NG 4      // batch groups (independent LSTM chains)
#define RG 32     // rows per group
#define CG 32     // CTAs per group (each owns 64 gate cols = 16 h cols)

// ---------------- scratch ----------------
__device__ __half g_xh[(size_t)Bb*Tt*Dd];     // 64 MB  x in fp16
__device__ __half g_wxh[(size_t)G4H*Dd];      // 1 MB   Wx in fp16
// xg in gate-interleaved layout: [t][b][j>>1][gate][j&1]  (2048 halves per (t,b))
__device__ __align__(16) __half g_xgh[(size_t)Tt*Bb*G4H];
__device__ __align__(16) __half g_hfh[2][Bb][Hh];  // h double buffer (fp16)
__device__ float  g_hT[Bb*Hh];                // final h (exact fp32)
__device__ unsigned g_bar4[NG * 4 * 32];      // per-(group,chunk) flags, 128B apart

// ---------------- PTX helpers ----------------
__device__ __forceinline__ unsigned smem_u32(const void* p) {
    return (unsigned)__cvta_generic_to_shared(p);
}
#define CPA16(dst, src) asm volatile("cp.async.cg.shared.global [%0], [%1], 16;\n" :: "r"(dst), "l"(src))
#define CPA_COMMIT()    asm volatile("cp.async.commit_group;\n")
#define CPA_WAIT(n)     asm volatile("cp.async.wait_group %0;\n" :: "n"(n))

__device__ __forceinline__ void ldm_x4(uint32_t* r, unsigned addr) {
    asm volatile("ldmatrix.sync.aligned.m8n8.x4.shared.b16 {%0,%1,%2,%3}, [%4];"
                 : "=r"(r[0]), "=r"(r[1]), "=r"(r[2]), "=r"(r[3]) : "r"(addr));
}
__device__ __forceinline__ void mma_f16(float* c, const uint32_t* a, uint32_t b0, uint32_t b1) {
    asm volatile("mma.sync.aligned.m16n8k16.row.col.f32.f16.f16.f32 "
                 "{%0,%1,%2,%3}, {%4,%5,%6,%7}, {%8,%9}, {%0,%1,%2,%3};"
                 : "+f"(c[0]), "+f"(c[1]), "+f"(c[2]), "+f"(c[3])
                 : "r"(a[0]), "r"(a[1]), "r"(a[2]), "r"(a[3]), "r"(b0), "r"(b1));
}
__device__ __forceinline__ unsigned ld_acq(const unsigned* p) {
    unsigned v; asm volatile("ld.acquire.gpu.u32 %0, [%1];" : "=r"(v) : "l"(p) : "memory"); return v;
}
__device__ __forceinline__ void red_rel(unsigned* p, unsigned v) {
    asm volatile("red.release.gpu.add.u32 [%0], %1;" :: "l"(p), "r"(v) : "memory");
}
__device__ __forceinline__ float fsig(float x)  { return 1.f / (1.f + __expf(-x)); }
__device__ __forceinline__ float ftanh(float x) { return 2.f / (1.f + __expf(-2.f * x)) - 1.f; }

// ---------------- phase 0: convert x, Wx to fp16 ----------------
__global__ void k_convert(const float* __restrict__ x, const float* __restrict__ Wx) {
    int64_t i = (int64_t)blockIdx.x * blockDim.x + threadIdx.x;
    int64_t stride = (int64_t)gridDim.x * blockDim.x;
    for (int64_t j = i; j < (int64_t)Bb*Tt*Dd / 4; j += stride) {
        float4 v = ((const float4*)x)[j];
        ((__half2*)g_xh)[j*2]   = __floats2half2_rn(v.x, v.y);
        ((__half2*)g_xh)[j*2+1] = __floats2half2_rn(v.z, v.w);
    }
    for (int64_t j = i; j < (int64_t)G4H*Dd / 4; j += stride) {
        float4 v = ((const float4*)Wx)[j];
        ((__half2*)g_wxh)[j*2]   = __floats2half2_rn(v.x, v.y);
        ((__half2*)g_wxh)[j*2+1] = __floats2half2_rn(v.z, v.w);
    }
}

// ---------------- phase 1: xg = x @ Wx^T + (bx+bh), fp16 mma, pipelined --------------
// CTA: one t (M=128 batch), N-tile=128. K=256 in 4 chunks of 64, 2-stage cp.async ring.
#define S1P 72   // fp16 row stride per chunk: 9 x 16B chunks (odd -> conflict-free)
#define STGP (128 * S1P)
__global__ void __launch_bounds__(256, 2) k_xg(const float* __restrict__ bx,
                                               const float* __restrict__ bh) {
    extern __shared__ char sm[];
    __half* Abuf = (__half*)sm;                    // 2 stages x [128][72]
    __half* Bbuf = Abuf + 2 * STGP;                // 2 stages x [128][72]
    const int tid = threadIdx.x, lane = tid & 31, wid = tid >> 5;
    const int t = blockIdx.y, nb0 = blockIdx.x * 128;
    const int warp_m = wid & 1, warp_n = wid >> 1; // 2x4 warps: M64 x N32 tiles

    auto issue = [&](int s) {
        __half* As = Abuf + (s & 1) * STGP;
        __half* Bs = Bbuf + (s & 1) * STGP;
        #pragma unroll
        for (int it = 0; it < 4; it++) {
            int task = tid + it * 256, b = task >> 3, c = task & 7;
            CPA16(smem_u32(As + b * S1P + c * 8),
                  g_xh + ((size_t)b * Tt + t) * Dd + s * 64 + c * 8);
        }
        #pragma unroll
        for (int it = 0; it < 4; it++) {
            int task = tid + it * 256, n = task >> 3, c = task & 7;
            CPA16(smem_u32(Bs + n * S1P + c * 8),
                  g_wxh + (size_t)(nb0 + n) * Dd + s * 64 + c * 8);
        }
        CPA_COMMIT();
    };

    issue(0);
    float acc[4][4][4] = {};
    #pragma unroll 1
    for (int s = 0; s < 4; s++) {
        __syncthreads();                 // all warps done with buffer (s+1)&1
        if (s < 3) { issue(s + 1); CPA_WAIT(1); }
        else       { CPA_WAIT(0); }
        __syncthreads();                 // stage s visible

        const __half* As = Abuf + (s & 1) * STGP;
        const __half* Bs = Bbuf + (s & 1) * STGP;
        #pragma unroll
        for (int kl = 0; kl < 4; kl++) {           // 4 k16-steps per chunk
            uint32_t a[4][4];
            #pragma unroll
            for (int mt = 0; mt < 4; mt++) {
                int r = warp_m * 64 + mt * 16 + (lane & 15);
                int c = kl * 16 + ((lane >> 4) << 3);
                ldm_x4(a[mt], smem_u32(As + r * S1P + c));
            }
            uint32_t bfr[4][2];
            #pragma unroll
            for (int ntp = 0; ntp < 2; ntp++) {
                int matrix = lane >> 3;
                int n = warp_n * 32 + ntp * 16 + ((matrix >> 1) << 3) + (lane & 7);
                int kcc = kl * 16 + ((matrix & 1) << 3);
                uint32_t r4[4];
                ldm_x4(r4, smem_u32(Bs + n * S1P + kcc));
                bfr[ntp*2][0] = r4[0];   bfr[ntp*2][1] = r4[1];
                bfr[ntp*2+1][0] = r4[2]; bfr[ntp*2+1][1] = r4[3];
            }
            #pragma unroll
            for (int mt = 0; mt < 4; mt++)
                #pragma unroll
                for (int nt = 0; nt < 4; nt++)
                    mma_f16(acc[mt][nt], a[mt], bfr[nt][0], bfr[nt][1]);
        }
    }
    // epilogue: exact fp32 bias, fp16 round, store in gate-interleaved layout
    const int group = lane >> 2, tc = lane & 3;
    #pragma unroll
    for (int mt = 0; mt < 4; mt++) {
        #pragma unroll
        for (int nt = 0; nt < 4; nt++) {
            int col = nb0 + warp_n * 32 + nt * 8 + tc * 2;   // global gate col (even)
            float b0 = __ldg(&bx[col]) + __ldg(&bh[col]);
            float b1 = __ldg(&bx[col + 1]) + __ldg(&bh[col + 1]);
            int gate = col >> 9, j = col & 511;              // j even
            int row0 = warp_m * 64 + mt * 16 + group;
            __half2 v0 = __floats2half2_rn(acc[mt][nt][0] + b0, acc[mt][nt][1] + b1);
            __half2 v1 = __floats2half2_rn(acc[mt][nt][2] + b0, acc[mt][nt][3] + b1);
            unsigned u0 = *reinterpret_cast<unsigned*>(&v0);
            unsigned u1 = *reinterpret_cast<unsigned*>(&v1);
            size_t base0 = ((size_t)(t * Bb + row0) * 256 + (j >> 1)) * 8 + gate * 2;
            size_t base1 = base0 + (size_t)8 * 2048;         // row0+8
            __stcs((unsigned*)&g_xgh[base0], u0);
            __stcs((unsigned*)&g_xgh[base1], u1);
        }
    }
}

// ---------------- phase 2: grouped LSTM recurrence — fp16, barrier-free staging ------
// 4 groups x 32 CTAs. CTA: M=32 rows, N=64 gate cols, K=512 over 4 warp K-chunks.
// Each warp stages its FULL 8KB chunk (tau partner writes identical bytes — benign
// dup) so no named barrier / partner skew. Wh fragments all in registers.
#define S2H 520   // fp16 row stride for h smem: 65 x 16B chunks (odd)
#define PB 72     // pbuf padded row stride (fp32)
__global__ void __launch_bounds__(256, 1) k_rec(const float* __restrict__ Wh) {
    extern __shared__ char sm[];
    __half* hb  = (__half*)sm;                     // [32][520] fp16   33280 B
    float* pbuf = (float*)(sm + RG * S2H * 2);     // [4][32][72] fp32 36864 B
    const int tid = threadIdx.x, lane = tid & 31, wid = tid >> 5;
    const int kc = wid >> 1, tau = wid & 1;        // K-chunk, N-half of this warp
    const int grp = blockIdx.x >> 5, cn = blockIdx.x & 31;
    const int colbase = cn * 16, row0 = grp * RG;
    unsigned* flags  = &g_bar4[grp * 4 * 32];
    unsigned* myflag = &flags[(cn >> 3) * 32];     // chunk this CTA's h slice feeds
    unsigned* kflag  = &flags[kc * 32];            // chunk this warp consumes

    // Build Wh B-fragments once (fp16, packed pairs) — ALL in registers.
    uint32_t breg[8][8];
    #pragma unroll
    for (int kl = 0; kl < 8; kl++) {
        #pragma unroll
        for (int nt = 0; nt < 4; nt++) {
            int n = tau * 32 + nt * 8 + (lane >> 2);      // local gate col 0..63
            int jj = n >> 2, gate = n & 3;
            const float* wp = Wh + (size_t)(gate * Hh + colbase + jj) * Hh;
            int k0 = kc * 128 + kl * 16 + (lane & 3) * 2;
            __half2 b0 = __floats2half2_rn(wp[k0], wp[k0 + 1]);
            __half2 b1 = __floats2half2_rn(wp[k0 + 8], wp[k0 + 9]);
            breg[kl][nt*2]   = *reinterpret_cast<uint32_t*>(&b0);
            breg[kl][nt*2+1] = *reinterpret_cast<uint32_t*>(&b1);
        }
    }
    // zero h0 slice, publish chunk readiness
    for (int tk = tid; tk < 512; tk += 256)
        g_hfh[0][row0 + (tk >> 4)][colbase + (tk & 15)] = __float2half(0.f);
    __syncthreads();
    if (tid == 0) red_rel(myflag, 1u);

    float cst[2] = {0.f, 0.f};                     // c-state per epilogue task

    for (int t = 0; t < Tt; t++) {
        // xg prefetch: one 16B load per task (gate-interleaved layout) — overlaps spin
        float xr[2][4];
        {
            #pragma unroll
            for (int s = 0; s < 2; s++) {
                int tk = tid + s * 256;
                int row = row0 + (tk >> 4), j = colbase + (tk & 15);
                const uint4* p = (const uint4*)
                    (g_xgh + ((size_t)(t * Bb + row) * 256 + (j >> 1)) * 8);
                uint4 q = __ldcs(p);
                __half2 h2;
                h2 = *reinterpret_cast<__half2*>(&q.x);
                xr[s][0] = (j & 1) ? __high2float(h2) : __low2float(h2);
                h2 = *reinterpret_cast<__half2*>(&q.y);
                xr[s][1] = (j & 1) ? __high2float(h2) : __low2float(h2);
                h2 = *reinterpret_cast<__half2*>(&q.z);
                xr[s][2] = (j & 1) ? __high2float(h2) : __low2float(h2);
                h2 = *reinterpret_cast<__half2*>(&q.w);
                xr[s][3] = (j & 1) ? __high2float(h2) : __low2float(h2);
            }
        }
        // per-warp spin: only this warp's K-chunk producers (8 CTAs)
        if (lane == 0) {
            unsigned tgt = 8u * (unsigned)(t + 1);
            while (ld_acq(kflag) < tgt) {}
        }
        __syncwarp();
        // stage FULL chunk kc (8 KB fp16); tau partner duplicates — no barrier needed
        {
            const __half* hsrc = &g_hfh[t & 1][row0][0];
            #pragma unroll
            for (int i = 0; i < 16; i++) {
                int task = lane + i * 32;
                int row = task >> 4, c16 = task & 15;
                int off = kc * 128 + c16 * 8;
                CPA16(smem_u32(hb + row * S2H + off), hsrc + (size_t)row * Hh + off);
            }
            CPA_COMMIT(); CPA_WAIT(0);
        }
        // MMA: M32 x N32(tau) x K128(kc), fp16 m16n8k16
        float acc[2][4][4] = {};
        #pragma unroll
        for (int kl = 0; kl < 8; kl++) {
            uint32_t a0[4], a1[4];
            int c = kc * 128 + kl * 16 + ((lane >> 4) << 3);
            int rr = lane & 15;
            ldm_x4(a0, smem_u32(hb + rr * S2H + c));
            ldm_x4(a1, smem_u32(hb + (rr + 16) * S2H + c));
            #pragma unroll
            for (int nt = 0; nt < 4; nt++) {
                mma_f16(acc[0][nt], a0, breg[kl][nt*2], breg[kl][nt*2+1]);
                mma_f16(acc[1][nt], a1, breg[kl][nt*2], breg[kl][nt*2+1]);
            }
        }
        // store K-partials in logical (row, gatecol) layout
        #pragma unroll
        for (int mt = 0; mt < 2; mt++) {
            #pragma unroll
            for (int nt = 0; nt < 4; nt++) {
                int r = mt * 16 + (lane >> 2);
                int n = tau * 32 + nt * 8 + (lane & 3) * 2;
                *(float2*)&pbuf[(kc * 32 + r) * PB + n] =
                    make_float2(acc[mt][nt][0], acc[mt][nt][1]);
                *(float2*)&pbuf[(kc * 32 + r + 8) * PB + n] =
                    make_float2(acc[mt][nt][2], acc[mt][nt][3]);
            }
        }
        __syncthreads();
        // reduce 4 K-partials + LSTM cell update per task, publish h_{t+1} (fp16)
        #pragma unroll
        for (int s = 0; s < 2; s++) {
            int tk = tid + s * 256;
            int row = tk >> 4, j = tk & 15;
            float4 sum = *(float4*)&pbuf[row * PB + j * 4];
            #pragma unroll
            for (int k = 1; k < 4; k++) {
                float4 p = *(float4*)&pbuf[(k * 32 + row) * PB + j * 4];
                sum.x += p.x; sum.y += p.y; sum.z += p.z; sum.w += p.w;
            }
            float pi = sum.x + xr[s][0];
            float pf = sum.y + xr[s][1];
            float pg = sum.z + xr[s][2];
            float po = sum.w + xr[s][3];
            float ii = fsig(pi), ff = fsig(pf), gg = ftanh(pg), oo = fsig(po);
            float cc = cst[s] * ff + ii * gg;
            cst[s] = cc;
            float hn = oo * ftanh(cc);
            g_hfh[(t + 1) & 1][row0 + row][colbase + j] = __float2half_rn(hn);
            if (t == Tt - 1) g_hT[(row0 + row) * Hh + colbase + j] = hn;  // exact
        }
        __syncthreads();                 // all publishes done before release
        if (tid == 0) red_rel(myflag, 1u);
    }
    // reset group flags for deterministic graph replay
    if (cn == 0 && tid == 0) {
        unsigned fin = 8u * (unsigned)(Tt + 1);
        for (int ch = 0; ch < 4; ch++) {
            while (ld_acq(&flags[ch * 32]) < fin) {}
            *(volatile unsigned*)&flags[ch * 32] = 0u;
        }
        __threadfence();
    }
}

// ---------------- phase 3: out = hT @ Wfc^T + bfc, plus hT copy ----------------
__global__ void k_fc(const float* __restrict__ Wfc, const float* __restrict__ bfc,
                     float* __restrict__ out, int out_size) {
    int gid = blockIdx.x * blockDim.x + threadIdx.x;
    int nthr = gridDim.x * blockDim.x;
    for (int i = gid; i < Bb * Hh && i < out_size; i += nthr) out[i] = g_hT[i];
    if (gid < Bb * Oo) {
        int b = gid >> 7, o = gid & 127;
        const float4* hp = (const float4*)&g_hT[b * Hh];
        const float4* wp = (const float4*)&Wfc[(size_t)o * Hh];
        float s = 0.f;
        #pragma unroll 8
        for (int k = 0; k < Hh / 4; k++) {
            float4 hv = hp[k], wv = wp[k];
            s += hv.x * wv.x + hv.y * wv.y + hv.z * wv.z + hv.w * wv.w;
        }
        int idx = Bb * Hh + gid;
        if (idx < out_size) out[idx] = s + bfc[o];
    }
}

// ---------------- launch ----------------
extern "C" void kernel_launch(void* const* d_in, const int* in_sizes, int n_in,
                              void* d_out, int out_size) {
    const float* x   = (const float*)d_in[0];
    const float* Wx  = (const float*)d_in[2];
    const float* bx  = (const float*)d_in[3];
    const float* Wh  = (const float*)d_in[4];
    const float* bh  = (const float*)d_in[5];
    const float* Wfc = (const float*)d_in[8];
    const float* bfc = (const float*)d_in[9];
    float* out = (float*)d_out;

    const int smem_xg  = 2 * 2 * STGP * 2;               // 73,728 B (2 CTAs/SM)
    const int smem_rec = RG * S2H * 2 + 4 * 32 * PB * 4; // 70,144 B
    cudaFuncSetAttribute(k_xg,  cudaFuncAttributeMaxDynamicSharedMemorySize, smem_xg);
    cudaFuncSetAttribute(k_rec, cudaFuncAttributeMaxDynamicSharedMemorySize, smem_rec);

    k_convert<<<1024, 256>>>(x, Wx);
    k_xg<<<dim3(16, 1024), 256, smem_xg>>>(bx, bh);
    k_rec<<<NG * CG, 256, smem_rec>>>(Wh);
    k_fc<<<256, 256>>>(Wfc, bfc, out, out_size);
}